// round 15
// baseline (speedup 1.0000x reference)
#include <cuda_runtime.h>
#include <cstdint>

// Problem constants (fixed by setup_inputs)
#define B_      16
#define T_      1024
#define D_      384
#define MAXDUR_ 4
#define OUTLEN_ (T_ * MAXDUR_)      // 4096
#define D4_     (D_ / 4)            // 96 float4 per row

#define NTHREADS     384
#define ROWS_PER_CTA 16             // 16 rows * 96 f4 = 1536 = 384 * 4
#define RPT          4              // rows per thread
#define GATHER_CTAS  (B_ * OUTLEN_ / ROWS_PER_CTA)   // 4096

// Scratch: per-output-frame source index, -1 => pad (zero fill)
__device__ int g_idx[B_ * OUTLEN_];
// Per-batch ready flags + self-resetting completion counter (epoch protocol:
// flags start 0 each launch; scan CTA b sets flag[b]=1; last gather CTA
// resets everything -> deterministic across graph replays).
__device__ volatile unsigned g_flag[B_];
__device__ unsigned g_done;

// ---------------------------------------------------------------------------
// Fused kernel. CTAs 0..15: scan role (compute g_idx for batch b, set flag).
// CTAs 16..16+4095: gather role (R2-proven body), spin on flag[b] first.
// Scan CTAs have the lowest blockIdx -> scheduled in wave 1 -> no deadlock.
// ---------------------------------------------------------------------------
__global__ void __launch_bounds__(NTHREADS) lr_fused(
    const float4* __restrict__ xs, const int* __restrict__ ds,
    float4* __restrict__ out) {

    __shared__ int sm_ds[T_];
    __shared__ int sm_excl[T_ / 4];
    __shared__ int sm_wsum[8];

    const int tid = threadIdx.x;

    if (blockIdx.x < B_) {
        // ================= scan role: batch b = blockIdx.x ==================
        const int b    = blockIdx.x;
        const int lane = tid & 31;

        int x = 0, psum = 0;
        if (tid < 256) {
            int4 v = __ldg(&((const int4*)(ds + b * T_))[tid]);
            ((int4*)sm_ds)[tid] = v;
            psum = v.x + v.y + v.z + v.w;
            x = psum;
            #pragma unroll
            for (int off = 1; off < 32; off <<= 1) {
                int y = __shfl_up_sync(0xffffffffu, x, off);
                if (lane >= off) x += y;
            }
            if (lane == 31) sm_wsum[tid >> 5] = x;
        }
        __syncthreads();
        if (tid < 256) {
            int base = 0;
            const int w = tid >> 5;
            #pragma unroll
            for (int i = 0; i < 8; i++) { int t = sm_wsum[i]; if (i < w) base += t; }
            sm_excl[tid] = base + x - psum;   // exclusive prefix of int4 group
        }
        __syncthreads();

        int total = 0;
        #pragma unroll
        for (int i = 0; i < 8; i++) total += sm_wsum[i];

        int* __restrict__ gi = &g_idx[b * OUTLEN_];

        // scatter: token t covers [start_t, start_t + d_t)
        for (int t = tid; t < T_; t += NTHREADS) {
            const int g = t >> 2;
            int s = sm_excl[g];
            for (int j = g << 2; j < t; j++) s += sm_ds[j];   // <=3 adds
            const int d = sm_ds[t];
            for (int k = 0; k < d; k++) gi[s + k] = t;
        }
        // pad tail
        for (int t = total + tid; t < OUTLEN_; t += NTHREADS) gi[t] = -1;

        __threadfence();               // publish g_idx to GPU scope
        __syncthreads();               // all scatter done before flag
        if (tid == 0) g_flag[b] = 1;   // release

    } else {
        // ================= gather role (R2-proven body) =====================
        const int cta  = blockIdx.x - B_;
        const int lr   = tid / D4_;            // 0..3
        const int c    = tid - lr * D4_;       // 0..95
        const int row0 = cta * ROWS_PER_CTA;
        const int b    = row0 >> 12;
        const float4* __restrict__ xb = xs + (size_t)b * T_ * D4_;

        if (tid == 0) {
            while (g_flag[b] == 0) __nanosleep(32);
            __threadfence();           // acquire: order g_idx loads after flag
        }
        __syncthreads();

        // batch the 4 independent idx loads
        int idxs[RPT];
        #pragma unroll
        for (int k = 0; k < RPT; k++)
            idxs[k] = g_idx[row0 + k * 4 + lr];

        // batch the 4 independent gathers
        float4 v[RPT];
        #pragma unroll
        for (int k = 0; k < RPT; k++) {
            if (idxs[k] >= 0)
                v[k] = __ldg(&xb[(size_t)idxs[k] * D4_ + c]);
            else
                v[k] = make_float4(0.f, 0.f, 0.f, 0.f);
        }

        // streaming stores (proven: evict-normal costs +6us in replay)
        #pragma unroll
        for (int k = 0; k < RPT; k++)
            __stcs(&out[(size_t)(row0 + k * 4 + lr) * D4_ + c], v[k]);

        // epoch reset: last gather CTA clears flags + counter for next replay
        if (tid == 0) {
            unsigned r = atomicAdd(&g_done, 1u);
            if (r == GATHER_CTAS - 1) {
                #pragma unroll
                for (int i = 0; i < B_; i++) g_flag[i] = 0;
                g_done = 0;
            }
        }
    }
}

extern "C" void kernel_launch(void* const* d_in, const int* in_sizes, int n_in,
                              void* d_out, int out_size) {
    const float* xs = (const float*)d_in[0];   // (16,1024,384) f32
    const int*   ds = (const int*)d_in[1];     // (16,1024) i32
    float* out = (float*)d_out;                // (16,4096,384) f32

    lr_fused<<<B_ + GATHER_CTAS, NTHREADS>>>(
        (const float4*)xs, ds, (float4*)out);
}

// round 16
// speedup vs baseline: 1.5019x; 1.5019x over previous
#include <cuda_runtime.h>
#include <cstdint>

// Problem constants (fixed by setup_inputs)
#define B_      16
#define T_      1024
#define D_      384
#define MAXDUR_ 4
#define OUTLEN_ (T_ * MAXDUR_)      // 4096
#define D4_     (D_ / 4)            // 96 float4 per row

#define NTHREADS     384
#define ROWS_PER_CTA 16             // 16 rows * 96 f4 = 1536 = 384 * 4
#define RPT          4              // rows per thread

// ---------------------------------------------------------------------------
// Single self-contained kernel: each CTA redundantly scans its batch's 1024
// durations (4KB, L2-broadcast across the 256 CTAs of the batch), builds the
// inclusive cumsum in smem, binary-searches the source index for its 16
// output rows, then runs the R2-proven gather body (__ldg reads, __stcs
// stores). No inter-CTA dependency, no second kernel, no index table.
// Grid: 4096 CTAs, 384 threads.
// ---------------------------------------------------------------------------
__global__ void __launch_bounds__(NTHREADS) lr_one_kernel(
    const float4* __restrict__ xs, const int* __restrict__ ds,
    float4* __restrict__ out) {

    __shared__ int sm_cs[T_];        // inclusive cumsum of durations
    __shared__ int sm_wsum[8];

    const int tid  = threadIdx.x;
    const int lane = tid & 31;
    const int row0 = blockIdx.x * ROWS_PER_CTA;
    const int b    = row0 >> 12;               // batch for whole CTA
    const int rloc = row0 & (OUTLEN_ - 1);     // row0 within batch

    // ---------------- prologue: redundant per-CTA scan ----------------------
    int4 dv = make_int4(0, 0, 0, 0);
    int x = 0, psum = 0;
    if (tid < 256) {
        dv = __ldg(&((const int4*)(ds + b * T_))[tid]);
        psum = dv.x + dv.y + dv.z + dv.w;
        x = psum;
        #pragma unroll
        for (int off = 1; off < 32; off <<= 1) {
            int y = __shfl_up_sync(0xffffffffu, x, off);
            if (lane >= off) x += y;
        }
        if (lane == 31) sm_wsum[tid >> 5] = x;
    }
    __syncthreads();
    if (tid < 256) {
        int base = 0;
        const int w = tid >> 5;
        #pragma unroll
        for (int i = 0; i < 8; i++) { int t = sm_wsum[i]; if (i < w) base += t; }
        const int excl = base + x - psum;      // exclusive prefix of my 4 tokens
        int c0 = excl + dv.x;
        int c1 = c0 + dv.y;
        int c2 = c1 + dv.z;
        int c3 = c2 + dv.w;
        ((int4*)sm_cs)[tid] = make_int4(c0, c1, c2, c3);
    }
    __syncthreads();

    const int total = sm_cs[T_ - 1];

    // ---------------- resolve source index for my 4 rows --------------------
    const int lr = tid / D4_;                  // 0..3
    const int c  = tid - lr * D4_;             // 0..95

    int idxs[RPT];
    #pragma unroll
    for (int k = 0; k < RPT; k++) {
        const int t = rloc + k * 4 + lr;       // output row within batch
        int idx = -1;
        if (t < total) {
            int lo = 0, hi = T_ - 1;           // first i with cs[i] > t
            #pragma unroll
            for (int s = 0; s < 10; s++) {
                const int mid = (lo + hi) >> 1;
                if (sm_cs[mid] > t) hi = mid; else lo = mid + 1;
            }
            idx = lo;
        }
        idxs[k] = idx;
    }

    // ---------------- R2-proven gather body ---------------------------------
    const float4* __restrict__ xb = xs + (size_t)b * T_ * D4_;

    float4 v[RPT];
    #pragma unroll
    for (int k = 0; k < RPT; k++) {
        if (idxs[k] >= 0)
            v[k] = __ldg(&xb[(size_t)idxs[k] * D4_ + c]);
        else
            v[k] = make_float4(0.f, 0.f, 0.f, 0.f);
    }

    // streaming stores (proven: evict-normal costs +6us in steady replay)
    #pragma unroll
    for (int k = 0; k < RPT; k++)
        __stcs(&out[(size_t)(row0 + k * 4 + lr) * D4_ + c], v[k]);
}

extern "C" void kernel_launch(void* const* d_in, const int* in_sizes, int n_in,
                              void* d_out, int out_size) {
    const float* xs = (const float*)d_in[0];   // (16,1024,384) f32
    const int*   ds = (const int*)d_in[1];     // (16,1024) i32
    float* out = (float*)d_out;                // (16,4096,384) f32

    lr_one_kernel<<<(B_ * OUTLEN_) / ROWS_PER_CTA, NTHREADS>>>(
        (const float4*)xs, ds, (float4*)out);
}

// round 17
// speedup vs baseline: 1.7954x; 1.1954x over previous
#include <cuda_runtime.h>
#include <cstdint>

// Problem constants (fixed by setup_inputs)
#define B_      16
#define T_      1024
#define D_      384
#define MAXDUR_ 4
#define OUTLEN_ (T_ * MAXDUR_)      // 4096
#define D4_     (D_ / 4)            // 96 float4 per row

#define G_THREADS    384            // gather CTA size
#define ROWS_PER_CTA 16             // 16 rows * 96 f4 = 1536 = 384 * 4
#define RPT          4              // rows per thread

#define S_THREADS    256            // scan CTA size
#define S_CTAS_PER_B 4              // 4 scan CTAs per batch (parallel scatter)
#define TOK_PER_SCTA (T_ / S_CTAS_PER_B)       // 256 tokens per scan CTA
#define PAD_PER_SCTA (OUTLEN_ / S_CTAS_PER_B)  // 1024 pad-candidate rows

// Scratch: per-output-frame source index, -1 => pad (zero fill)
__device__ int g_idx[B_ * OUTLEN_];

// ---------------------------------------------------------------------------
// Kernel 1: parallel scan+scatter. 64 CTAs (4 per batch) x 256 threads.
// Each CTA redundantly computes the full batch scan (int4 loads, single-level
// warp scan, warp sums folded in-register -> ONE syncthreads), then scatters
// only its 256-token slice and its quarter of the pad tail. 4x the scatter
// parallelism and half the sync rounds of the R2 scan.
// ---------------------------------------------------------------------------
__global__ void __launch_bounds__(S_THREADS) scan_idx_kernel(const int* __restrict__ ds) {
    __shared__ int sm_wsum[8];

    const int b    = blockIdx.x >> 2;          // batch
    const int cb   = blockIdx.x & 3;           // slice within batch
    const int tid  = threadIdx.x;
    const int lane = tid & 31;
    const int warp = tid >> 5;

    // full-batch load: 256 threads x int4 = 1024 durations
    int4 dv = __ldg(&((const int4*)(ds + b * T_))[tid]);
    const int psum = dv.x + dv.y + dv.z + dv.w;

    // warp inclusive scan of per-thread sums
    int x = psum;
    #pragma unroll
    for (int off = 1; off < 32; off <<= 1) {
        int y = __shfl_up_sync(0xffffffffu, x, off);
        if (lane >= off) x += y;
    }
    if (lane == 31) sm_wsum[warp] = x;
    __syncthreads();

    // fold the 8 warp totals in-register (no second sync)
    int base = 0, total = 0;
    #pragma unroll
    for (int i = 0; i < 8; i++) {
        const int t = sm_wsum[i];
        if (i < warp) base += t;
        total += t;
    }
    const int excl = base + x - psum;          // exclusive prefix of my 4 tokens

    int* __restrict__ gi = &g_idx[b * OUTLEN_];

    // scatter only my CTA's token slice: tokens [cb*256, cb*256+256)
    // my 4 tokens are 4*tid .. 4*tid+3; slice test on the int4 group
    if ((tid >> 6) == cb) {
        int s = excl;
        const int tok0 = tid << 2;
        const int dvs[4] = {dv.x, dv.y, dv.z, dv.w};
        #pragma unroll
        for (int j = 0; j < 4; j++) {
            const int d = dvs[j];
            for (int k = 0; k < d; k++) gi[s + k] = tok0 + j;
            s += d;
        }
    }

    // pad tail, sliced: CTA cb covers rows [cb*1024, cb*1024+1024)
    const int p0 = cb * PAD_PER_SCTA;
    const int p1 = p0 + PAD_PER_SCTA;
    int t0 = total > p0 ? total : p0;
    for (int t = t0 + tid; t < p1; t += S_THREADS) gi[t] = -1;
}

// ---------------------------------------------------------------------------
// Kernel 2: streaming gather — EXACT R2 config (best measured: 18.8us ncu,
// 21.0us harness). __ldg reads, MLP=4, __stcs stores. DO NOT TOUCH.
// ---------------------------------------------------------------------------
__global__ void __launch_bounds__(G_THREADS) gather_kernel(
    const float4* __restrict__ xs, float4* __restrict__ out) {
    const int lr   = threadIdx.x / D4_;        // 0..3 local row within slice
    const int c    = threadIdx.x - lr * D4_;   // 0..95 column
    const int row0 = blockIdx.x * ROWS_PER_CTA;
    const int b    = row0 >> 12;               // same batch for whole CTA
    const float4* __restrict__ xb = xs + (size_t)b * T_ * D4_;

    // batch the 4 independent idx loads
    int idxs[RPT];
    #pragma unroll
    for (int k = 0; k < RPT; k++)
        idxs[k] = g_idx[row0 + k * 4 + lr];

    // batch the 4 independent gathers
    float4 v[RPT];
    #pragma unroll
    for (int k = 0; k < RPT; k++) {
        if (idxs[k] >= 0)
            v[k] = __ldg(&xb[(size_t)idxs[k] * D4_ + c]);
        else
            v[k] = make_float4(0.f, 0.f, 0.f, 0.f);
    }

    // streaming stores: keep 100MB of write-once data from squatting in L2
    #pragma unroll
    for (int k = 0; k < RPT; k++)
        __stcs(&out[(size_t)(row0 + k * 4 + lr) * D4_ + c], v[k]);
}

extern "C" void kernel_launch(void* const* d_in, const int* in_sizes, int n_in,
                              void* d_out, int out_size) {
    const float* xs = (const float*)d_in[0];   // (16,1024,384) f32
    const int*   ds = (const int*)d_in[1];     // (16,1024) i32
    float* out = (float*)d_out;                // (16,4096,384) f32

    scan_idx_kernel<<<B_ * S_CTAS_PER_B, S_THREADS>>>(ds);
    gather_kernel<<<(B_ * OUTLEN_) / ROWS_PER_CTA, G_THREADS>>>(
        (const float4*)xs, (float4*)out);
}